// round 6
// baseline (speedup 1.0000x reference)
#include <cuda_runtime.h>

#define D_MODEL 1024
#define NUM_HEADS 16
#define DK 64
#define BATCH 2
#define SEQ 2048
#define MTOT (BATCH*SEQ)   // 4096

// Scratch (no allocations allowed): Q, K, V, attention-output O. 16 MB each.
__device__ float g_Q[MTOT * D_MODEL];
__device__ float g_K[MTOT * D_MODEL];
__device__ float g_V[MTOT * D_MODEL];
__device__ float g_O[MTOT * D_MODEL];

// ---------------------------------------------------------------------------
// C[M,N] = A[M,K] @ W[K,N] + bias[N]
// 64x64 tile, 256 threads, 4x4 register tile per thread, k-tile = 16.
// ---------------------------------------------------------------------------
__global__ __launch_bounds__(256) void gemm_bias_kernel(
    const float* __restrict__ A, const float* __restrict__ W,
    const float* __restrict__ bias, float* __restrict__ C,
    int M, int N, int K)
{
    __shared__ float As[16][64];   // [k][m]  (A stored transposed)
    __shared__ float Bs[16][64];   // [k][n]

    const int tid = threadIdx.x;
    const int tx = tid & 15, ty = tid >> 4;
    const int m0 = blockIdx.y << 6, n0 = blockIdx.x << 6;

    // A-tile load mapping: 64 rows x 16 k, one float4 per thread
    const int ar = tid >> 2;           // 0..63
    const int ak = (tid & 3) << 2;     // 0,4,8,12
    // B-tile load mapping: 16 k x 64 n
    const int br = tid >> 4;           // 0..15
    const int bn = (tid & 15) << 2;    // 0..60

    float acc[4][4];
#pragma unroll
    for (int i = 0; i < 4; i++)
#pragma unroll
        for (int j = 0; j < 4; j++) acc[i][j] = 0.f;

    for (int k0 = 0; k0 < K; k0 += 16) {
        float4 av = *(const float4*)(A + (size_t)(m0 + ar) * K + k0 + ak);
        As[ak + 0][ar] = av.x;
        As[ak + 1][ar] = av.y;
        As[ak + 2][ar] = av.z;
        As[ak + 3][ar] = av.w;
        *(float4*)(&Bs[br][bn]) =
            *(const float4*)(W + (size_t)(k0 + br) * N + n0 + bn);
        __syncthreads();

#pragma unroll
        for (int kk = 0; kk < 16; kk++) {
            float4 a4 = *(const float4*)&As[kk][ty << 2];
            float4 b4 = *(const float4*)&Bs[kk][tx << 2];
            float a[4] = {a4.x, a4.y, a4.z, a4.w};
            float b[4] = {b4.x, b4.y, b4.z, b4.w};
#pragma unroll
            for (int i = 0; i < 4; i++)
#pragma unroll
                for (int j = 0; j < 4; j++)
                    acc[i][j] += a[i] * b[j];
        }
        __syncthreads();
    }

    float4 bv = *(const float4*)(bias + n0 + (tx << 2));
#pragma unroll
    for (int i = 0; i < 4; i++) {
        float4 o;
        o.x = acc[i][0] + bv.x;
        o.y = acc[i][1] + bv.y;
        o.z = acc[i][2] + bv.z;
        o.w = acc[i][3] + bv.w;
        *(float4*)(C + (size_t)(m0 + (ty << 2) + i) * N + n0 + (tx << 2)) = o;
    }
}

// ---------------------------------------------------------------------------
// Fused attention, one (b, h, 64-query-row tile) per CTA.
// Online softmax (flash style). Q scaled by 1/sqrt(Dk)=0.125 at load.
// Smem = Qt(16K) + KtP(16K, K-transposed then reused for P) + Vs(16K) = 48KB.
// ---------------------------------------------------------------------------
__global__ __launch_bounds__(256) void attn_kernel(
    const float* __restrict__ Qg, const float* __restrict__ Kg,
    const float* __restrict__ Vg, float* __restrict__ Og)
{
    __shared__ float Qt[DK][64];    // [d][q-row]
    __shared__ float KtP[64][64];   // phase A: K^T [d][k-row]; phase B: P [q-row][k-row]
    __shared__ float Vs[64][DK];    // [k-row][d]

    const int tid = threadIdx.x;
    const int tx = tid & 15, ty = tid >> 4;
    const int q0 = blockIdx.x << 6;
    const int h = blockIdx.y, b = blockIdx.z;
    const size_t hb = (size_t)b * SEQ * D_MODEL + (size_t)h * DK;

    const int lr  = tid >> 2;          // 0..63  (row within tile)
    const int ld0 = (tid & 3) << 2;    // 0,4,8,12

    // Load Q tile transposed + pre-scaled
#pragma unroll
    for (int db = 0; db < 4; db++) {
        int d = (db << 4) + ld0;
        float4 qv = *(const float4*)(Qg + hb + (size_t)(q0 + lr) * D_MODEL + d);
        Qt[d + 0][lr] = qv.x * 0.125f;
        Qt[d + 1][lr] = qv.y * 0.125f;
        Qt[d + 2][lr] = qv.z * 0.125f;
        Qt[d + 3][lr] = qv.w * 0.125f;
    }

    float m_i[4], l_i[4], acc[4][4];
#pragma unroll
    for (int i = 0; i < 4; i++) {
        m_i[i] = -1e30f; l_i[i] = 0.f;
#pragma unroll
        for (int j = 0; j < 4; j++) acc[i][j] = 0.f;
    }

    for (int k0 = 0; k0 < SEQ; k0 += 64) {
        __syncthreads();   // previous-iteration readers of KtP/Vs are done

        // Load K (transposed) and V (natural)
#pragma unroll
        for (int db = 0; db < 4; db++) {
            int d = (db << 4) + ld0;
            float4 kv = *(const float4*)(Kg + hb + (size_t)(k0 + lr) * D_MODEL + d);
            KtP[d + 0][lr] = kv.x;
            KtP[d + 1][lr] = kv.y;
            KtP[d + 2][lr] = kv.z;
            KtP[d + 3][lr] = kv.w;
            *(float4*)(&Vs[lr][d]) =
                *(const float4*)(Vg + hb + (size_t)(k0 + lr) * D_MODEL + d);
        }
        __syncthreads();

        // S = Q @ K^T  (4x4 per thread)
        float s[4][4];
#pragma unroll
        for (int i = 0; i < 4; i++)
#pragma unroll
            for (int j = 0; j < 4; j++) s[i][j] = 0.f;

#pragma unroll 4
        for (int dk = 0; dk < DK; dk++) {
            float4 qv = *(const float4*)&Qt[dk][ty << 2];
            float4 kv = *(const float4*)&KtP[dk][tx << 2];
            float qa[4] = {qv.x, qv.y, qv.z, qv.w};
            float ka[4] = {kv.x, kv.y, kv.z, kv.w};
#pragma unroll
            for (int i = 0; i < 4; i++)
#pragma unroll
                for (int j = 0; j < 4; j++)
                    s[i][j] += qa[i] * ka[j];
        }

        // Online softmax update. Row r = ty*4+i is owned by the 16 threads with
        // this ty (half-warp, lanes differ only in bits 0-3) -> xor-shuffle 1..8.
#pragma unroll
        for (int i = 0; i < 4; i++) {
            float mx = fmaxf(fmaxf(s[i][0], s[i][1]), fmaxf(s[i][2], s[i][3]));
#pragma unroll
            for (int off = 1; off < 16; off <<= 1)
                mx = fmaxf(mx, __shfl_xor_sync(0xffffffffu, mx, off));
            float mnew  = fmaxf(m_i[i], mx);
            float alpha = __expf(m_i[i] - mnew);
            float rs = 0.f;
#pragma unroll
            for (int j = 0; j < 4; j++) {
                float p = __expf(s[i][j] - mnew);
                s[i][j] = p;
                rs += p;
            }
#pragma unroll
            for (int off = 1; off < 16; off <<= 1)
                rs += __shfl_xor_sync(0xffffffffu, rs, off);
            l_i[i] = l_i[i] * alpha + rs;
            m_i[i] = mnew;
#pragma unroll
            for (int j = 0; j < 4; j++) acc[i][j] *= alpha;
        }

        __syncthreads();   // everyone finished reading KtP as K
#pragma unroll
        for (int i = 0; i < 4; i++)
            *(float4*)(&KtP[(ty << 2) + i][tx << 2]) =
                make_float4(s[i][0], s[i][1], s[i][2], s[i][3]);
        __syncthreads();

        // acc += P @ V
#pragma unroll 4
        for (int kk4 = 0; kk4 < 16; kk4++) {
            float p[4][4], vv[4][4];
#pragma unroll
            for (int i = 0; i < 4; i++) {
                float4 t = *(const float4*)&KtP[(ty << 2) + i][kk4 << 2];
                p[i][0] = t.x; p[i][1] = t.y; p[i][2] = t.z; p[i][3] = t.w;
            }
#pragma unroll
            for (int q = 0; q < 4; q++) {
                float4 t = *(const float4*)&Vs[(kk4 << 2) + q][tx << 2];
                vv[q][0] = t.x; vv[q][1] = t.y; vv[q][2] = t.z; vv[q][3] = t.w;
            }
#pragma unroll
            for (int i = 0; i < 4; i++)
#pragma unroll
                for (int j = 0; j < 4; j++)
#pragma unroll
                    for (int q = 0; q < 4; q++)
                        acc[i][j] += p[i][q] * vv[q][j];
        }
    }

    // Epilogue: normalize and write O in [B,S,H*Dk] layout
#pragma unroll
    for (int i = 0; i < 4; i++) {
        float rl = 1.f / l_i[i];
        float4 o = make_float4(acc[i][0] * rl, acc[i][1] * rl,
                               acc[i][2] * rl, acc[i][3] * rl);
        *(float4*)(Og + hb + (size_t)(q0 + (ty << 2) + i) * D_MODEL + (tx << 2)) = o;
    }
}

// ---------------------------------------------------------------------------
extern "C" void kernel_launch(void* const* d_in, const int* in_sizes, int n_in,
                              void* d_out, int out_size)
{
    const float* x  = (const float*)d_in[0];
    const float* Wq = (const float*)d_in[1];
    const float* bq = (const float*)d_in[2];
    const float* Wk = (const float*)d_in[3];
    const float* bk = (const float*)d_in[4];
    const float* Wv = (const float*)d_in[5];
    const float* bv = (const float*)d_in[6];
    const float* Wo = (const float*)d_in[7];
    const float* bo = (const float*)d_in[8];
    float* out = (float*)d_out;

    float *Qp, *Kp, *Vp, *Op;
    cudaGetSymbolAddress((void**)&Qp, g_Q);
    cudaGetSymbolAddress((void**)&Kp, g_K);
    cudaGetSymbolAddress((void**)&Vp, g_V);
    cudaGetSymbolAddress((void**)&Op, g_O);

    dim3 gg(D_MODEL / 64, MTOT / 64);   // (16, 64)
    gemm_bias_kernel<<<gg, 256>>>(x, Wq, bq, Qp, MTOT, D_MODEL, D_MODEL);
    gemm_bias_kernel<<<gg, 256>>>(x, Wk, bk, Kp, MTOT, D_MODEL, D_MODEL);
    gemm_bias_kernel<<<gg, 256>>>(x, Wv, bv, Vp, MTOT, D_MODEL, D_MODEL);

    dim3 ga(SEQ / 64, NUM_HEADS, BATCH);  // (32, 16, 2)
    attn_kernel<<<ga, 256>>>(Qp, Kp, Vp, Op);

    gemm_bias_kernel<<<gg, 256>>>(Op, Wo, bo, out, MTOT, D_MODEL, D_MODEL);
}

// round 11
// speedup vs baseline: 1.5285x; 1.5285x over previous
#include <cuda_runtime.h>
#include <cstdint>

#define D_MODEL 1024
#define NUM_HEADS 16
#define DK 64
#define BATCH 2
#define SEQ 2048
#define MTOT (BATCH*SEQ)   // 4096

// Scratch (no allocations allowed): Q, K, V, attention-output O.
__device__ float g_Q[MTOT * D_MODEL];
__device__ float g_K[MTOT * D_MODEL];
__device__ float g_V[MTOT * D_MODEL];
__device__ float g_O[MTOT * D_MODEL];

// ===========================================================================
// Helpers
// ===========================================================================
__device__ __forceinline__ uint32_t f2tf32(float f) {
    uint32_t r;
    asm("cvt.rna.tf32.f32 %0, %1;" : "=r"(r) : "f"(f));
    return r;
}
__device__ __forceinline__ void mma_tf32(float c[4], const uint32_t a[4],
                                         const uint32_t b[2]) {
    asm volatile(
        "mma.sync.aligned.m16n8k8.row.col.f32.tf32.tf32.f32 "
        "{%0,%1,%2,%3}, {%4,%5,%6,%7}, {%8,%9}, {%0,%1,%2,%3};"
        : "+f"(c[0]), "+f"(c[1]), "+f"(c[2]), "+f"(c[3])
        : "r"(a[0]), "r"(a[1]), "r"(a[2]), "r"(a[3]), "r"(b[0]), "r"(b[1]));
}

// ===========================================================================
// mma.sync tf32 GEMM:  C[M,N] = A[M,K] @ W[K,N] + bias   (M=4096, N=K=1024)
// CTA tile 128x128, 256 threads (8 warps, 2x4), warp tile 64x32, k-tile 32.
// Smem: As [m][k] stride 36 (pad), Bs [k][n] stride 136 (pad), double buffer.
// ===========================================================================
#define TM 128
#define TN 128
#define TKT 32
#define NKT (D_MODEL / TKT)      // 32
#define ASTR 36                   // A smem row stride (words)
#define BSTR 136                  // B smem row stride (words)
#define ABYTES (TM * ASTR * 4)    // 18432
#define BBYTES (TKT * BSTR * 4)   // 17408
#define BUFW ((ABYTES + BBYTES) / 4)   // buffer stride in words (8960)
#define GSMEM_BYTES (2 * (ABYTES + BBYTES))  // 71680

__global__ __launch_bounds__(256, 1) void gemm_tc(
    const float* __restrict__ A, const float* __restrict__ W,
    const float* __restrict__ bias, float* __restrict__ C)
{
    extern __shared__ uint32_t smw[];

    const int tid = threadIdx.x;
    const int wid = tid >> 5;
    const int lane = tid & 31;
    const int g = lane >> 2;          // groupID 0..7
    const int tig = lane & 3;         // thread-in-group 0..3
    const int wy = wid & 1;           // 2 warps along M (64 rows each)
    const int wx = wid >> 1;          // 4 warps along N (32 cols each)
    const int m0 = blockIdx.y * TM, n0 = blockIdx.x * TN;

    // Global-load mappings
    const int ar_row = tid >> 3;            // 0..31 (+128 per it? no: f>>3)
    // A: 1024 float4 per k-tile: f = tid + it*256 -> row=f>>3, kc=f&7
    // B: f -> kr=f>>5, nc=f&31

    float acc[4][4][4];
#pragma unroll
    for (int mi = 0; mi < 4; mi++)
#pragma unroll
        for (int ni = 0; ni < 4; ni++)
#pragma unroll
            for (int c = 0; c < 4; c++) acc[mi][ni][c] = 0.f;

    float4 ar[4], br[4];

    // prologue load k-tile 0
#pragma unroll
    for (int it = 0; it < 4; it++) {
        int f = tid + (it << 8);
        ar[it] = *(const float4*)(A + (size_t)(m0 + (f >> 3)) * D_MODEL + ((f & 7) << 2));
        br[it] = *(const float4*)(W + (size_t)(f >> 5) * D_MODEL + n0 + ((f & 31) << 2));
    }

    for (int i = 0; i < NKT; i++) {
        const int b = i & 1;
        uint32_t* sA = smw + b * BUFW;
        uint32_t* sB = sA + (ABYTES / 4);

        // store staged tile (with tf32 rounding)
#pragma unroll
        for (int it = 0; it < 4; it++) {
            int f = tid + (it << 8);
            int row = f >> 3, kc = f & 7;
            uint32_t* p = sA + row * ASTR + (kc << 2);
            p[0] = f2tf32(ar[it].x); p[1] = f2tf32(ar[it].y);
            p[2] = f2tf32(ar[it].z); p[3] = f2tf32(ar[it].w);
            int kr = f >> 5, nc = f & 31;
            uint32_t* q = sB + kr * BSTR + (nc << 2);
            q[0] = f2tf32(br[it].x); q[1] = f2tf32(br[it].y);
            q[2] = f2tf32(br[it].z); q[3] = f2tf32(br[it].w);
        }
        __syncthreads();

        // stage next k-tile from global
        if (i < NKT - 1) {
            const int k0 = (i + 1) * TKT;
#pragma unroll
            for (int it = 0; it < 4; it++) {
                int f = tid + (it << 8);
                ar[it] = *(const float4*)(A + (size_t)(m0 + (f >> 3)) * D_MODEL
                                          + k0 + ((f & 7) << 2));
                br[it] = *(const float4*)(W + (size_t)(k0 + (f >> 5)) * D_MODEL
                                          + n0 + ((f & 31) << 2));
            }
        }

        // compute on buffer b
        const uint32_t* Ab = sA + (wy << 6) * ASTR;   // warp's 64 M-rows
        const uint32_t* Bb = sB + (wx << 5);          // warp's 32 N-cols
#pragma unroll
        for (int ks = 0; ks < 4; ks++) {
            uint32_t af[4][4], bf[4][2];
            const int kk = (ks << 3) + tig;
#pragma unroll
            for (int mi = 0; mi < 4; mi++) {
                const uint32_t* p = Ab + ((mi << 4) + g) * ASTR + kk;
                af[mi][0] = p[0];
                af[mi][1] = p[8 * ASTR];
                af[mi][2] = p[4];
                af[mi][3] = p[8 * ASTR + 4];
            }
#pragma unroll
            for (int ni = 0; ni < 4; ni++) {
                const uint32_t* p = Bb + kk * BSTR + (ni << 3) + g;
                bf[ni][0] = p[0];
                bf[ni][1] = p[4 * BSTR];
            }
#pragma unroll
            for (int mi = 0; mi < 4; mi++)
#pragma unroll
                for (int ni = 0; ni < 4; ni++)
                    mma_tf32(acc[mi][ni], af[mi], bf[ni]);
        }
        __syncthreads();
    }

    // Epilogue: c0,c1 -> (row, 2tig..+1), c2,c3 -> (row+8, ...)
#pragma unroll
    for (int ni = 0; ni < 4; ni++) {
        const int col = n0 + (wx << 5) + (ni << 3) + (tig << 1);
        const float2 bv = *(const float2*)(bias + col);
#pragma unroll
        for (int mi = 0; mi < 4; mi++) {
            const int r0 = m0 + (wy << 6) + (mi << 4) + g;
            float2 o0 = make_float2(acc[mi][ni][0] + bv.x, acc[mi][ni][1] + bv.y);
            float2 o1 = make_float2(acc[mi][ni][2] + bv.x, acc[mi][ni][3] + bv.y);
            *(float2*)(C + (size_t)r0 * D_MODEL + col) = o0;
            *(float2*)(C + (size_t)(r0 + 8) * D_MODEL + col) = o1;
        }
    }
}

// ---------------------------------------------------------------------------
// Fused attention (unchanged, proven): one (b, h, 64-q-row tile) per CTA.
// ---------------------------------------------------------------------------
__global__ __launch_bounds__(256) void attn_kernel(
    const float* __restrict__ Qg, const float* __restrict__ Kg,
    const float* __restrict__ Vg, float* __restrict__ Og)
{
    __shared__ float Qt[DK][64];
    __shared__ float KtP[64][64];
    __shared__ float Vs[64][DK];

    const int tid = threadIdx.x;
    const int tx = tid & 15, ty = tid >> 4;
    const int q0 = blockIdx.x << 6;
    const int h = blockIdx.y, b = blockIdx.z;
    const size_t hb = (size_t)b * SEQ * D_MODEL + (size_t)h * DK;

    const int lr  = tid >> 2;
    const int ld0 = (tid & 3) << 2;

#pragma unroll
    for (int db = 0; db < 4; db++) {
        int d = (db << 4) + ld0;
        float4 qv = *(const float4*)(Qg + hb + (size_t)(q0 + lr) * D_MODEL + d);
        Qt[d + 0][lr] = qv.x * 0.125f;
        Qt[d + 1][lr] = qv.y * 0.125f;
        Qt[d + 2][lr] = qv.z * 0.125f;
        Qt[d + 3][lr] = qv.w * 0.125f;
    }

    float m_i[4], l_i[4], acc[4][4];
#pragma unroll
    for (int i = 0; i < 4; i++) {
        m_i[i] = -1e30f; l_i[i] = 0.f;
#pragma unroll
        for (int j = 0; j < 4; j++) acc[i][j] = 0.f;
    }

    for (int k0 = 0; k0 < SEQ; k0 += 64) {
        __syncthreads();
#pragma unroll
        for (int db = 0; db < 4; db++) {
            int d = (db << 4) + ld0;
            float4 kv = *(const float4*)(Kg + hb + (size_t)(k0 + lr) * D_MODEL + d);
            KtP[d + 0][lr] = kv.x;
            KtP[d + 1][lr] = kv.y;
            KtP[d + 2][lr] = kv.z;
            KtP[d + 3][lr] = kv.w;
            *(float4*)(&Vs[lr][d]) =
                *(const float4*)(Vg + hb + (size_t)(k0 + lr) * D_MODEL + d);
        }
        __syncthreads();

        float s[4][4];
#pragma unroll
        for (int i = 0; i < 4; i++)
#pragma unroll
            for (int j = 0; j < 4; j++) s[i][j] = 0.f;

#pragma unroll 4
        for (int dk = 0; dk < DK; dk++) {
            float4 qv = *(const float4*)&Qt[dk][ty << 2];
            float4 kv = *(const float4*)&KtP[dk][tx << 2];
            float qa[4] = {qv.x, qv.y, qv.z, qv.w};
            float ka[4] = {kv.x, kv.y, kv.z, kv.w};
#pragma unroll
            for (int i = 0; i < 4; i++)
#pragma unroll
                for (int j = 0; j < 4; j++)
                    s[i][j] += qa[i] * ka[j];
        }

#pragma unroll
        for (int i = 0; i < 4; i++) {
            float mx = fmaxf(fmaxf(s[i][0], s[i][1]), fmaxf(s[i][2], s[i][3]));
#pragma unroll
            for (int off = 1; off < 16; off <<= 1)
                mx = fmaxf(mx, __shfl_xor_sync(0xffffffffu, mx, off));
            float mnew  = fmaxf(m_i[i], mx);
            float alpha = __expf(m_i[i] - mnew);
            float rs = 0.f;
#pragma unroll
            for (int j = 0; j < 4; j++) {
                float p = __expf(s[i][j] - mnew);
                s[i][j] = p;
                rs += p;
            }
#pragma unroll
            for (int off = 1; off < 16; off <<= 1)
                rs += __shfl_xor_sync(0xffffffffu, rs, off);
            l_i[i] = l_i[i] * alpha + rs;
            m_i[i] = mnew;
#pragma unroll
            for (int j = 0; j < 4; j++) acc[i][j] *= alpha;
        }

        __syncthreads();
#pragma unroll
        for (int i = 0; i < 4; i++)
            *(float4*)(&KtP[(ty << 2) + i][tx << 2]) =
                make_float4(s[i][0], s[i][1], s[i][2], s[i][3]);
        __syncthreads();

#pragma unroll 4
        for (int kk4 = 0; kk4 < 16; kk4++) {
            float p[4][4], vv[4][4];
#pragma unroll
            for (int i = 0; i < 4; i++) {
                float4 t = *(const float4*)&KtP[(ty << 2) + i][kk4 << 2];
                p[i][0] = t.x; p[i][1] = t.y; p[i][2] = t.z; p[i][3] = t.w;
            }
#pragma unroll
            for (int q = 0; q < 4; q++) {
                float4 t = *(const float4*)&Vs[(kk4 << 2) + q][tx << 2];
                vv[q][0] = t.x; vv[q][1] = t.y; vv[q][2] = t.z; vv[q][3] = t.w;
            }
#pragma unroll
            for (int i = 0; i < 4; i++)
#pragma unroll
                for (int j = 0; j < 4; j++)
#pragma unroll
                    for (int q = 0; q < 4; q++)
                        acc[i][j] += p[i][q] * vv[q][j];
        }
    }

#pragma unroll
    for (int i = 0; i < 4; i++) {
        float rl = 1.f / l_i[i];
        float4 o = make_float4(acc[i][0] * rl, acc[i][1] * rl,
                               acc[i][2] * rl, acc[i][3] * rl);
        *(float4*)(Og + hb + (size_t)(q0 + (ty << 2) + i) * D_MODEL + (tx << 2)) = o;
    }
}

// ---------------------------------------------------------------------------
extern "C" void kernel_launch(void* const* d_in, const int* in_sizes, int n_in,
                              void* d_out, int out_size)
{
    const float* x  = (const float*)d_in[0];
    const float* Wq = (const float*)d_in[1];
    const float* bq = (const float*)d_in[2];
    const float* Wk = (const float*)d_in[3];
    const float* bk = (const float*)d_in[4];
    const float* Wv = (const float*)d_in[5];
    const float* bv = (const float*)d_in[6];
    const float* Wo = (const float*)d_in[7];
    const float* bo = (const float*)d_in[8];
    float* out = (float*)d_out;

    float *Qp, *Kp, *Vp, *Op;
    cudaGetSymbolAddress((void**)&Qp, g_Q);
    cudaGetSymbolAddress((void**)&Kp, g_K);
    cudaGetSymbolAddress((void**)&Vp, g_V);
    cudaGetSymbolAddress((void**)&Op, g_O);

    cudaFuncSetAttribute(gemm_tc, cudaFuncAttributeMaxDynamicSharedMemorySize,
                         GSMEM_BYTES);

    dim3 gg(D_MODEL / TN, MTOT / TM);   // (8, 32)
    gemm_tc<<<gg, 256, GSMEM_BYTES>>>(x, Wq, bq, Qp);
    gemm_tc<<<gg, 256, GSMEM_BYTES>>>(x, Wk, bk, Kp);
    gemm_tc<<<gg, 256, GSMEM_BYTES>>>(x, Wv, bv, Vp);

    dim3 ga(SEQ / 64, NUM_HEADS, BATCH);  // (32, 16, 2)
    attn_kernel<<<ga, 256>>>(Qp, Kp, Vp, Op);

    gemm_tc<<<gg, 256, GSMEM_BYTES>>>(Op, Wo, bo, out);
}

// round 14
// speedup vs baseline: 1.6663x; 1.0901x over previous
#include <cuda_runtime.h>
#include <cstdint>

#define D_MODEL 1024
#define NUM_HEADS 16
#define DK 64
#define BATCH 2
#define SEQ 2048
#define MTOT (BATCH*SEQ)   // 4096

typedef unsigned long long u64;

// Scratch (no allocations allowed): Q, K, V, attention-output O.
__device__ float g_Q[MTOT * D_MODEL];
__device__ float g_K[MTOT * D_MODEL];
__device__ float g_V[MTOT * D_MODEL];
__device__ float g_O[MTOT * D_MODEL];

// ===========================================================================
// Helpers
// ===========================================================================
__device__ __forceinline__ uint32_t f2tf32(float f) {
    uint32_t r;
    asm("cvt.rna.tf32.f32 %0, %1;" : "=r"(r) : "f"(f));
    return r;
}
__device__ __forceinline__ void mma_tf32(float c[4], const uint32_t a[4],
                                         const uint32_t b[2]) {
    asm volatile(
        "mma.sync.aligned.m16n8k8.row.col.f32.tf32.tf32.f32 "
        "{%0,%1,%2,%3}, {%4,%5,%6,%7}, {%8,%9}, {%0,%1,%2,%3};"
        : "+f"(c[0]), "+f"(c[1]), "+f"(c[2]), "+f"(c[3])
        : "r"(a[0]), "r"(a[1]), "r"(a[2]), "r"(a[3]), "r"(b[0]), "r"(b[1]));
}
// Packed fp32x2 ops (full fp32 precision, 2x FFMA issue rate)
__device__ __forceinline__ u64 pack2(float lo, float hi) {
    u64 r;
    asm("mov.b64 %0, {%1, %2};" : "=l"(r) : "f"(lo), "f"(hi));
    return r;
}
__device__ __forceinline__ void unpack2(u64 v, float& lo, float& hi) {
    asm("mov.b64 {%0, %1}, %2;" : "=f"(lo), "=f"(hi) : "l"(v));
}
__device__ __forceinline__ void fma2(u64& c, u64 a, u64 b) {
    asm("fma.rn.f32x2 %0, %1, %2, %0;" : "+l"(c) : "l"(a), "l"(b));
}
__device__ __forceinline__ void mul2(u64& c, u64 a) {
    asm("mul.rn.f32x2 %0, %0, %1;" : "+l"(c) : "l"(a));
}

// ===========================================================================
// mma.sync tf32 GEMM (unchanged from R11):  C = A @ W + bias
// ===========================================================================
#define TM 128
#define TN 128
#define TKT 32
#define NKT (D_MODEL / TKT)
#define ASTR 36
#define BSTR 136
#define ABYTES (TM * ASTR * 4)
#define BBYTES (TKT * BSTR * 4)
#define BUFW ((ABYTES + BBYTES) / 4)
#define GSMEM_BYTES (2 * (ABYTES + BBYTES))

__global__ __launch_bounds__(256, 1) void gemm_tc(
    const float* __restrict__ A, const float* __restrict__ W,
    const float* __restrict__ bias, float* __restrict__ C)
{
    extern __shared__ uint32_t smw[];

    const int tid = threadIdx.x;
    const int wid = tid >> 5;
    const int lane = tid & 31;
    const int g = lane >> 2;
    const int tig = lane & 3;
    const int wy = wid & 1;
    const int wx = wid >> 1;
    const int m0 = blockIdx.y * TM, n0 = blockIdx.x * TN;

    float acc[4][4][4];
#pragma unroll
    for (int mi = 0; mi < 4; mi++)
#pragma unroll
        for (int ni = 0; ni < 4; ni++)
#pragma unroll
            for (int c = 0; c < 4; c++) acc[mi][ni][c] = 0.f;

    float4 ar[4], br[4];
#pragma unroll
    for (int it = 0; it < 4; it++) {
        int f = tid + (it << 8);
        ar[it] = *(const float4*)(A + (size_t)(m0 + (f >> 3)) * D_MODEL + ((f & 7) << 2));
        br[it] = *(const float4*)(W + (size_t)(f >> 5) * D_MODEL + n0 + ((f & 31) << 2));
    }

    for (int i = 0; i < NKT; i++) {
        const int b = i & 1;
        uint32_t* sA = smw + b * BUFW;
        uint32_t* sB = sA + (ABYTES / 4);

#pragma unroll
        for (int it = 0; it < 4; it++) {
            int f = tid + (it << 8);
            int row = f >> 3, kc = f & 7;
            uint32_t* p = sA + row * ASTR + (kc << 2);
            p[0] = f2tf32(ar[it].x); p[1] = f2tf32(ar[it].y);
            p[2] = f2tf32(ar[it].z); p[3] = f2tf32(ar[it].w);
            int kr = f >> 5, nc = f & 31;
            uint32_t* q = sB + kr * BSTR + (nc << 2);
            q[0] = f2tf32(br[it].x); q[1] = f2tf32(br[it].y);
            q[2] = f2tf32(br[it].z); q[3] = f2tf32(br[it].w);
        }
        __syncthreads();

        if (i < NKT - 1) {
            const int k0 = (i + 1) * TKT;
#pragma unroll
            for (int it = 0; it < 4; it++) {
                int f = tid + (it << 8);
                ar[it] = *(const float4*)(A + (size_t)(m0 + (f >> 3)) * D_MODEL
                                          + k0 + ((f & 7) << 2));
                br[it] = *(const float4*)(W + (size_t)(k0 + (f >> 5)) * D_MODEL
                                          + n0 + ((f & 31) << 2));
            }
        }

        const uint32_t* Ab = sA + (wy << 6) * ASTR;
        const uint32_t* Bb = sB + (wx << 5);
#pragma unroll
        for (int ks = 0; ks < 4; ks++) {
            uint32_t af[4][4], bf[4][2];
            const int kk = (ks << 3) + tig;
#pragma unroll
            for (int mi = 0; mi < 4; mi++) {
                const uint32_t* p = Ab + ((mi << 4) + g) * ASTR + kk;
                af[mi][0] = p[0];
                af[mi][1] = p[8 * ASTR];
                af[mi][2] = p[4];
                af[mi][3] = p[8 * ASTR + 4];
            }
#pragma unroll
            for (int ni = 0; ni < 4; ni++) {
                const uint32_t* p = Bb + kk * BSTR + (ni << 3) + g;
                bf[ni][0] = p[0];
                bf[ni][1] = p[4 * BSTR];
            }
#pragma unroll
            for (int mi = 0; mi < 4; mi++)
#pragma unroll
                for (int ni = 0; ni < 4; ni++)
                    mma_tf32(acc[mi][ni], af[mi], bf[ni]);
        }
        __syncthreads();
    }

#pragma unroll
    for (int ni = 0; ni < 4; ni++) {
        const int col = n0 + (wx << 5) + (ni << 3) + (tig << 1);
        const float2 bv = *(const float2*)(bias + col);
#pragma unroll
        for (int mi = 0; mi < 4; mi++) {
            const int r0 = m0 + (wy << 6) + (mi << 4) + g;
            float2 o0 = make_float2(acc[mi][ni][0] + bv.x, acc[mi][ni][1] + bv.y);
            float2 o1 = make_float2(acc[mi][ni][2] + bv.x, acc[mi][ni][3] + bv.y);
            *(float2*)(C + (size_t)r0 * D_MODEL + col) = o0;
            *(float2*)(C + (size_t)(r0 + 8) * D_MODEL + col) = o1;
        }
    }
}

// ===========================================================================
// Attention v2: packed-f32x2 FFMA, q-tile 128 x k-tile 64, 256 threads,
// 2 CTAs/SM. Thread (ty,tx) owns 8 q-rows (ty*8..) x 4 k-cols (tx*4..),
// accumulators packed over q-pairs. P stored [k][q] for pair-direct PV loads.
// ===========================================================================
#define AQT 128
#define AKT 64
#define QSTR 132               // Qt: [d][q], 64 x 132 words
#define KSTR 68                // Kt: [d][k], 64 x 68
#define PSTR 132               // P:  [k][q], 64 x 132
#define QT_OFF 0
#define KT_OFF (64 * QSTR)                 // 8448
#define V_OFF  (KT_OFF + 64 * KSTR)        // 12800  V: [k][dk] 64x64
#define P_OFF  (V_OFF + 64 * 64)           // 16896
#define ATTN_SMEM_B ((P_OFF + 64 * PSTR) * 4)   // 101376

__global__ __launch_bounds__(256, 2) void attn_kernel(
    const float* __restrict__ Qg, const float* __restrict__ Kg,
    const float* __restrict__ Vg, float* __restrict__ Og)
{
    extern __shared__ float sm[];
    float* Qt = sm + QT_OFF;
    float* Kt = sm + KT_OFF;
    float* Vs = sm + V_OFF;
    float* Pm = sm + P_OFF;

    const int tid = threadIdx.x;
    const int tx = tid & 15, ty = tid >> 4;
    const int q0 = blockIdx.x << 7;
    const int h = blockIdx.y, b = blockIdx.z;
    const size_t hb = (size_t)b * SEQ * D_MODEL + (size_t)h * DK;

    // Load Q tile (128 x 64), transposed + pre-scaled: Qt[d][q]
#pragma unroll
    for (int it = 0; it < 8; it++) {
        int f = tid + (it << 8);
        int row = f >> 4, c4 = (f & 15) << 2;
        float4 qv = *(const float4*)(Qg + hb + (size_t)(q0 + row) * D_MODEL + c4);
        Qt[(c4 + 0) * QSTR + row] = qv.x * 0.125f;
        Qt[(c4 + 1) * QSTR + row] = qv.y * 0.125f;
        Qt[(c4 + 2) * QSTR + row] = qv.z * 0.125f;
        Qt[(c4 + 3) * QSTR + row] = qv.w * 0.125f;
    }

    u64 o2[4][4];
    float m_i[8], l_i[8];
#pragma unroll
    for (int p = 0; p < 4; p++)
#pragma unroll
        for (int d = 0; d < 4; d++) o2[p][d] = 0ull;
#pragma unroll
    for (int r = 0; r < 8; r++) { m_i[r] = -1e30f; l_i[r] = 0.f; }

    for (int kt = 0; kt < SEQ / AKT; kt++) {
        const int k0 = kt * AKT;
        __syncthreads();   // previous iteration's smem readers done

        // Load K (transposed -> Kt[d][k]) and V (natural) tiles, 64 rows
#pragma unroll
        for (int it = 0; it < 4; it++) {
            int f = tid + (it << 8);
            int row = f >> 4, c4 = (f & 15) << 2;
            float4 kv = *(const float4*)(Kg + hb + (size_t)(k0 + row) * D_MODEL + c4);
            Kt[(c4 + 0) * KSTR + row] = kv.x;
            Kt[(c4 + 1) * KSTR + row] = kv.y;
            Kt[(c4 + 2) * KSTR + row] = kv.z;
            Kt[(c4 + 3) * KSTR + row] = kv.w;
            *(float4*)(Vs + row * 64 + c4) =
                *(const float4*)(Vg + hb + (size_t)(k0 + row) * D_MODEL + c4);
        }
        __syncthreads();

        // S = Q @ K^T : s2[p][j] = packed (q-rows 2p,2p+1) x k-col tx*4+j
        u64 s2[4][4];
#pragma unroll
        for (int p = 0; p < 4; p++)
#pragma unroll
            for (int j = 0; j < 4; j++) s2[p][j] = 0ull;

#pragma unroll 4
        for (int d = 0; d < DK; d++) {
            ulonglong2 qa = *(const ulonglong2*)(Qt + d * QSTR + (ty << 3));
            ulonglong2 qb = *(const ulonglong2*)(Qt + d * QSTR + (ty << 3) + 4);
            float4 kf = *(const float4*)(Kt + d * KSTR + (tx << 2));
            u64 k2[4] = { pack2(kf.x, kf.x), pack2(kf.y, kf.y),
                          pack2(kf.z, kf.z), pack2(kf.w, kf.w) };
            u64 qp[4] = { qa.x, qa.y, qb.x, qb.y };
#pragma unroll
            for (int p = 0; p < 4; p++)
#pragma unroll
                for (int j = 0; j < 4; j++)
                    fma2(s2[p][j], qp[p], k2[j]);
        }

        // Online softmax per q-row (rows spread over 16 tx lanes)
#pragma unroll
        for (int p = 0; p < 4; p++) {
            float lo[4], hi[4];
#pragma unroll
            for (int j = 0; j < 4; j++) unpack2(s2[p][j], lo[j], hi[j]);

            float mx0 = fmaxf(fmaxf(lo[0], lo[1]), fmaxf(lo[2], lo[3]));
            float mx1 = fmaxf(fmaxf(hi[0], hi[1]), fmaxf(hi[2], hi[3]));
#pragma unroll
            for (int off = 1; off < 16; off <<= 1) {
                mx0 = fmaxf(mx0, __shfl_xor_sync(0xffffffffu, mx0, off));
                mx1 = fmaxf(mx1, __shfl_xor_sync(0xffffffffu, mx1, off));
            }
            float mn0 = fmaxf(m_i[2 * p], mx0);
            float mn1 = fmaxf(m_i[2 * p + 1], mx1);
            float al0 = __expf(m_i[2 * p] - mn0);
            float al1 = __expf(m_i[2 * p + 1] - mn1);
            float s0 = 0.f, s1 = 0.f;
#pragma unroll
            for (int j = 0; j < 4; j++) {
                lo[j] = __expf(lo[j] - mn0); s0 += lo[j];
                hi[j] = __expf(hi[j] - mn1); s1 += hi[j];
            }
#pragma unroll
            for (int off = 1; off < 16; off <<= 1) {
                s0 += __shfl_xor_sync(0xffffffffu, s0, off);
                s1 += __shfl_xor_sync(0xffffffffu, s1, off);
            }
            l_i[2 * p]     = l_i[2 * p] * al0 + s0;     m_i[2 * p] = mn0;
            l_i[2 * p + 1] = l_i[2 * p + 1] * al1 + s1; m_i[2 * p + 1] = mn1;
#pragma unroll
            for (int j = 0; j < 4; j++) s2[p][j] = pack2(lo[j], hi[j]);
            u64 a2 = pack2(al0, al1);
#pragma unroll
            for (int d = 0; d < 4; d++) mul2(o2[p][d], a2);
        }

        // Store P[k][q] (k row = tx*4+j, q cols = ty*8+2p..)
#pragma unroll
        for (int j = 0; j < 4; j++)
#pragma unroll
            for (int p = 0; p < 4; p++)
                *(u64*)(Pm + ((tx << 2) + j) * PSTR + (ty << 3) + 2 * p) = s2[p][j];
        __syncthreads();

        // O += P @ V : o2[p][dk], dk cols = tx*4..+3
#pragma unroll 4
        for (int k = 0; k < AKT; k++) {
            ulonglong2 pa = *(const ulonglong2*)(Pm + k * PSTR + (ty << 3));
            ulonglong2 pb = *(const ulonglong2*)(Pm + k * PSTR + (ty << 3) + 4);
            float4 vf = *(const float4*)(Vs + k * 64 + (tx << 2));
            u64 v2[4] = { pack2(vf.x, vf.x), pack2(vf.y, vf.y),
                          pack2(vf.z, vf.z), pack2(vf.w, vf.w) };
            u64 pp[4] = { pa.x, pa.y, pb.x, pb.y };
#pragma unroll
            for (int p = 0; p < 4; p++)
#pragma unroll
                for (int d = 0; d < 4; d++)
                    fma2(o2[p][d], pp[p], v2[d]);
        }
    }

    // Epilogue: normalize, write O in [B,S,H*Dk]
#pragma unroll
    for (int p = 0; p < 4; p++) {
        float e0[4], e1[4];
#pragma unroll
        for (int d = 0; d < 4; d++) unpack2(o2[p][d], e0[d], e1[d]);
        float rl0 = 1.f / l_i[2 * p], rl1 = 1.f / l_i[2 * p + 1];
        int row = q0 + (ty << 3) + 2 * p;
        float4 w0 = make_float4(e0[0] * rl0, e0[1] * rl0, e0[2] * rl0, e0[3] * rl0);
        float4 w1 = make_float4(e1[0] * rl1, e1[1] * rl1, e1[2] * rl1, e1[3] * rl1);
        *(float4*)(Og + hb + (size_t)row * D_MODEL + (tx << 2)) = w0;
        *(float4*)(Og + hb + (size_t)(row + 1) * D_MODEL + (tx << 2)) = w1;
    }
}

// ---------------------------------------------------------------------------
extern "C" void kernel_launch(void* const* d_in, const int* in_sizes, int n_in,
                              void* d_out, int out_size)
{
    const float* x  = (const float*)d_in[0];
    const float* Wq = (const float*)d_in[1];
    const float* bq = (const float*)d_in[2];
    const float* Wk = (const float*)d_in[3];
    const float* bk = (const float*)d_in[4];
    const float* Wv = (const float*)d_in[5];
    const float* bv = (const float*)d_in[6];
    const float* Wo = (const float*)d_in[7];
    const float* bo = (const float*)d_in[8];
    float* out = (float*)d_out;

    float *Qp, *Kp, *Vp, *Op;
    cudaGetSymbolAddress((void**)&Qp, g_Q);
    cudaGetSymbolAddress((void**)&Kp, g_K);
    cudaGetSymbolAddress((void**)&Vp, g_V);
    cudaGetSymbolAddress((void**)&Op, g_O);

    cudaFuncSetAttribute(gemm_tc, cudaFuncAttributeMaxDynamicSharedMemorySize,
                         GSMEM_BYTES);
    cudaFuncSetAttribute(attn_kernel, cudaFuncAttributeMaxDynamicSharedMemorySize,
                         ATTN_SMEM_B);

    dim3 gg(D_MODEL / TN, MTOT / TM);   // (8, 32)
    gemm_tc<<<gg, 256, GSMEM_BYTES>>>(x, Wq, bq, Qp);
    gemm_tc<<<gg, 256, GSMEM_BYTES>>>(x, Wk, bk, Kp);
    gemm_tc<<<gg, 256, GSMEM_BYTES>>>(x, Wv, bv, Vp);

    dim3 ga(SEQ / AQT, NUM_HEADS, BATCH);  // (16, 16, 2)
    attn_kernel<<<ga, 256, ATTN_SMEM_B>>>(Qp, Kp, Vp, Op);

    gemm_tc<<<gg, 256, GSMEM_BYTES>>>(Op, Wo, bo, out);
}

// round 16
// speedup vs baseline: 3.1898x; 1.9143x over previous
#include <cuda_runtime.h>
#include <cstdint>

#define D_MODEL 1024
#define NUM_HEADS 16
#define DK 64
#define BATCH 2
#define SEQ 2048
#define MTOT (BATCH*SEQ)   // 4096

// Scratch (no allocations allowed): Q, K, V, attention-output O.
__device__ float g_Q[MTOT * D_MODEL];
__device__ float g_K[MTOT * D_MODEL];
__device__ float g_V[MTOT * D_MODEL];
__device__ float g_O[MTOT * D_MODEL];

// ===========================================================================
// Helpers
// ===========================================================================
__device__ __forceinline__ uint32_t f2tf32(float f) {
    uint32_t r;
    asm("cvt.rna.tf32.f32 %0, %1;" : "=r"(r) : "f"(f));
    return r;
}
__device__ __forceinline__ float fex2(float x) {   // fast 2^x (MUFU.EX2)
    float r;
    asm("ex2.approx.f32 %0, %1;" : "=f"(r) : "f"(x));
    return r;
}
__device__ __forceinline__ void mma_tf32(float c[4], const uint32_t a[4],
                                         const uint32_t b[2]) {
    asm volatile(
        "mma.sync.aligned.m16n8k8.row.col.f32.tf32.tf32.f32 "
        "{%0,%1,%2,%3}, {%4,%5,%6,%7}, {%8,%9}, {%0,%1,%2,%3};"
        : "+f"(c[0]), "+f"(c[1]), "+f"(c[2]), "+f"(c[3])
        : "r"(a[0]), "r"(a[1]), "r"(a[2]), "r"(a[3]), "r"(b[0]), "r"(b[1]));
}

// ===========================================================================
// mma.sync tf32 GEMM (unchanged, proven 74us):  C = A @ W + bias
// ===========================================================================
#define TM 128
#define TN 128
#define TKT 32
#define NKT (D_MODEL / TKT)
#define ASTR 36
#define BSTR 136
#define ABYTES (TM * ASTR * 4)
#define BBYTES (TKT * BSTR * 4)
#define BUFW ((ABYTES + BBYTES) / 4)
#define GSMEM_BYTES (2 * (ABYTES + BBYTES))

__global__ __launch_bounds__(256, 1) void gemm_tc(
    const float* __restrict__ A, const float* __restrict__ W,
    const float* __restrict__ bias, float* __restrict__ C)
{
    extern __shared__ uint32_t smw[];

    const int tid = threadIdx.x;
    const int wid = tid >> 5;
    const int lane = tid & 31;
    const int g = lane >> 2;
    const int tig = lane & 3;
    const int wy = wid & 1;
    const int wx = wid >> 1;
    const int m0 = blockIdx.y * TM, n0 = blockIdx.x * TN;

    float acc[4][4][4];
#pragma unroll
    for (int mi = 0; mi < 4; mi++)
#pragma unroll
        for (int ni = 0; ni < 4; ni++)
#pragma unroll
            for (int c = 0; c < 4; c++) acc[mi][ni][c] = 0.f;

    float4 ar[4], br[4];
#pragma unroll
    for (int it = 0; it < 4; it++) {
        int f = tid + (it << 8);
        ar[it] = *(const float4*)(A + (size_t)(m0 + (f >> 3)) * D_MODEL + ((f & 7) << 2));
        br[it] = *(const float4*)(W + (size_t)(f >> 5) * D_MODEL + n0 + ((f & 31) << 2));
    }

    for (int i = 0; i < NKT; i++) {
        const int b = i & 1;
        uint32_t* sA = smw + b * BUFW;
        uint32_t* sB = sA + (ABYTES / 4);

#pragma unroll
        for (int it = 0; it < 4; it++) {
            int f = tid + (it << 8);
            int row = f >> 3, kc = f & 7;
            uint32_t* p = sA + row * ASTR + (kc << 2);
            p[0] = f2tf32(ar[it].x); p[1] = f2tf32(ar[it].y);
            p[2] = f2tf32(ar[it].z); p[3] = f2tf32(ar[it].w);
            int kr = f >> 5, nc = f & 31;
            uint32_t* q = sB + kr * BSTR + (nc << 2);
            q[0] = f2tf32(br[it].x); q[1] = f2tf32(br[it].y);
            q[2] = f2tf32(br[it].z); q[3] = f2tf32(br[it].w);
        }
        __syncthreads();

        if (i < NKT - 1) {
            const int k0 = (i + 1) * TKT;
#pragma unroll
            for (int it = 0; it < 4; it++) {
                int f = tid + (it << 8);
                ar[it] = *(const float4*)(A + (size_t)(m0 + (f >> 3)) * D_MODEL
                                          + k0 + ((f & 7) << 2));
                br[it] = *(const float4*)(W + (size_t)(k0 + (f >> 5)) * D_MODEL
                                          + n0 + ((f & 31) << 2));
            }
        }

        const uint32_t* Ab = sA + (wy << 6) * ASTR;
        const uint32_t* Bb = sB + (wx << 5);
#pragma unroll
        for (int ks = 0; ks < 4; ks++) {
            uint32_t af[4][4], bf[4][2];
            const int kk = (ks << 3) + tig;
#pragma unroll
            for (int mi = 0; mi < 4; mi++) {
                const uint32_t* p = Ab + ((mi << 4) + g) * ASTR + kk;
                af[mi][0] = p[0];
                af[mi][1] = p[8 * ASTR];
                af[mi][2] = p[4];
                af[mi][3] = p[8 * ASTR + 4];
            }
#pragma unroll
            for (int ni = 0; ni < 4; ni++) {
                const uint32_t* p = Bb + kk * BSTR + (ni << 3) + g;
                bf[ni][0] = p[0];
                bf[ni][1] = p[4 * BSTR];
            }
#pragma unroll
            for (int mi = 0; mi < 4; mi++)
#pragma unroll
                for (int ni = 0; ni < 4; ni++)
                    mma_tf32(acc[mi][ni], af[mi], bf[ni]);
        }
        __syncthreads();
    }

#pragma unroll
    for (int ni = 0; ni < 4; ni++) {
        const int col = n0 + (wx << 5) + (ni << 3) + (tig << 1);
        const float2 bv = *(const float2*)(bias + col);
#pragma unroll
        for (int mi = 0; mi < 4; mi++) {
            const int r0 = m0 + (wy << 6) + (mi << 4) + g;
            float2 o0 = make_float2(acc[mi][ni][0] + bv.x, acc[mi][ni][1] + bv.y);
            float2 o1 = make_float2(acc[mi][ni][2] + bv.x, acc[mi][ni][3] + bv.y);
            *(float2*)(C + (size_t)r0 * D_MODEL + col) = o0;
            *(float2*)(C + (size_t)(r0 + 8) * D_MODEL + col) = o1;
        }
    }
}

// ===========================================================================
// Attention v3: tensor-core (mma.sync tf32) flash attention.
// CTA: 128 q-rows, k-tile 64, 256 threads = 8 warps, each warp 16 q-rows.
// Natural-layout K (stride 68) and V (stride 72) serve as col-major B frags
// conflict-free. Q fragments in registers. P round-trips smem as tf32.
// Softmax in log2 domain (Q pre-scaled by 0.125*log2(e)).
// Smem: Qs/P alias [128][68] + K [64][68] + V [64][72] = 70656 B. 2 CTAs/SM.
// ===========================================================================
#define AQT 128
#define AKT 64
#define QPSTR 68
#define AKSTR 68
#define AVSTR 72
#define QP_OFF 0
#define AK_OFF (128 * QPSTR)              // 8704
#define AV_OFF (AK_OFF + 64 * AKSTR)      // 13056
#define ATTN_WORDS (AV_OFF + 64 * AVSTR)  // 17664
#define ATTN_SMEM_B (ATTN_WORDS * 4)      // 70656

#define QK_SCALE 0.18033688f   // 0.125 * log2(e)

__global__ __launch_bounds__(256, 2) void attn_kernel(
    const float* __restrict__ Qg, const float* __restrict__ Kg,
    const float* __restrict__ Vg, float* __restrict__ Og)
{
    extern __shared__ uint32_t smu[];
    uint32_t* QP = smu + QP_OFF;   // Qs (prologue) then P (mainloop)
    uint32_t* Ks = smu + AK_OFF;
    uint32_t* Vs = smu + AV_OFF;

    const int tid = threadIdx.x;
    const int wid = tid >> 5;
    const int lane = tid & 31;
    const int g = lane >> 2;
    const int tig = lane & 3;
    const int qw = wid << 4;             // warp q-base in tile (0..112)
    const int q0 = blockIdx.x << 7;
    const int h = blockIdx.y, b = blockIdx.z;
    const size_t hb = (size_t)b * SEQ * D_MODEL + (size_t)h * DK;

    // ---- Prologue: Q tile -> Qs (scaled, tf32) ----
#pragma unroll
    for (int it = 0; it < 8; it++) {
        int f = tid + (it << 8);
        int row = f >> 4, c4 = (f & 15) << 2;
        float4 qv = *(const float4*)(Qg + hb + (size_t)(q0 + row) * D_MODEL + c4);
        uint32_t* p = QP + row * QPSTR + c4;
        p[0] = f2tf32(qv.x * QK_SCALE);
        p[1] = f2tf32(qv.y * QK_SCALE);
        p[2] = f2tf32(qv.z * QK_SCALE);
        p[3] = f2tf32(qv.w * QK_SCALE);
    }
    __syncthreads();

    // ---- Q fragments to registers (reused for all 32 k-tiles) ----
    uint32_t qf[8][4];
#pragma unroll
    for (int ks = 0; ks < 8; ks++) {
        const uint32_t* p = QP + (qw + g) * QPSTR + (ks << 3) + tig;
        qf[ks][0] = p[0];
        qf[ks][1] = p[8 * QPSTR];
        qf[ks][2] = p[4];
        qf[ks][3] = p[8 * QPSTR + 4];
    }

    float o[8][4];
#pragma unroll
    for (int ni = 0; ni < 8; ni++)
#pragma unroll
        for (int c = 0; c < 4; c++) o[ni][c] = 0.f;
    float m0r = -1e30f, m1r = -1e30f, l0 = 0.f, l1 = 0.f;

    for (int kt = 0; kt < SEQ / AKT; kt++) {
        const int k0 = kt * AKT;
        __syncthreads();   // previous iteration's K/V/P readers done
                           // (also orders qf reads before first P write)

        // ---- Load K, V tiles (natural layout, tf32) ----
#pragma unroll
        for (int it = 0; it < 4; it++) {
            int f = tid + (it << 8);
            int row = f >> 4, c4 = (f & 15) << 2;
            float4 kv = *(const float4*)(Kg + hb + (size_t)(k0 + row) * D_MODEL + c4);
            uint4 kk = make_uint4(f2tf32(kv.x), f2tf32(kv.y), f2tf32(kv.z), f2tf32(kv.w));
            *(uint4*)(Ks + row * AKSTR + c4) = kk;
            float4 vv = *(const float4*)(Vg + hb + (size_t)(k0 + row) * D_MODEL + c4);
            uint4 vu = make_uint4(f2tf32(vv.x), f2tf32(vv.y), f2tf32(vv.z), f2tf32(vv.w));
            *(uint4*)(Vs + row * AVSTR + c4) = vu;
        }
        __syncthreads();

        // ---- S = Q @ K^T  (warp: 16q x 64k, 8 n-tiles x 8 k-steps) ----
        float s[8][4];
#pragma unroll
        for (int ni = 0; ni < 8; ni++)
#pragma unroll
            for (int c = 0; c < 4; c++) s[ni][c] = 0.f;

#pragma unroll
        for (int ks = 0; ks < 8; ks++) {
            const int kk = (ks << 3) + tig;
#pragma unroll
            for (int ni = 0; ni < 8; ni++) {
                uint32_t bf[2];
                const uint32_t* p = Ks + ((ni << 3) + g) * AKSTR + kk;
                bf[0] = p[0];
                bf[1] = p[4];
                mma_tf32(s[ni], qf[ks], bf);
            }
        }

        // ---- Online softmax (rows g, g+8 of warp tile; log2 domain) ----
        float mx0 = -1e30f, mx1 = -1e30f;
#pragma unroll
        for (int ni = 0; ni < 8; ni++) {
            mx0 = fmaxf(mx0, fmaxf(s[ni][0], s[ni][1]));
            mx1 = fmaxf(mx1, fmaxf(s[ni][2], s[ni][3]));
        }
#pragma unroll
        for (int off = 1; off < 4; off <<= 1) {
            mx0 = fmaxf(mx0, __shfl_xor_sync(0xffffffffu, mx0, off));
            mx1 = fmaxf(mx1, __shfl_xor_sync(0xffffffffu, mx1, off));
        }
        const float mn0 = fmaxf(m0r, mx0);
        const float mn1 = fmaxf(m1r, mx1);
        const float al0 = fex2(m0r - mn0);
        const float al1 = fex2(m1r - mn1);
        m0r = mn0; m1r = mn1;

        float sum0 = 0.f, sum1 = 0.f;
        uint32_t pr[8][4];
#pragma unroll
        for (int ni = 0; ni < 8; ni++) {
            float p0 = fex2(s[ni][0] - mn0);
            float p1 = fex2(s[ni][1] - mn0);
            float p2 = fex2(s[ni][2] - mn1);
            float p3 = fex2(s[ni][3] - mn1);
            pr[ni][0] = f2tf32(p0); pr[ni][1] = f2tf32(p1);
            pr[ni][2] = f2tf32(p2); pr[ni][3] = f2tf32(p3);
            // sum the rounded values so l exactly normalizes stored P
            sum0 += __uint_as_float(pr[ni][0]) + __uint_as_float(pr[ni][1]);
            sum1 += __uint_as_float(pr[ni][2]) + __uint_as_float(pr[ni][3]);
        }
#pragma unroll
        for (int off = 1; off < 4; off <<= 1) {
            sum0 += __shfl_xor_sync(0xffffffffu, sum0, off);
            sum1 += __shfl_xor_sync(0xffffffffu, sum1, off);
        }
        l0 = l0 * al0 + sum0;
        l1 = l1 * al1 + sum1;

        // rescale O accumulators
#pragma unroll
        for (int ni = 0; ni < 8; ni++) {
            o[ni][0] *= al0; o[ni][1] *= al0;
            o[ni][2] *= al1; o[ni][3] *= al1;
        }

        // ---- Store P fragments (rows qw+g, qw+g+8) ----
#pragma unroll
        for (int ni = 0; ni < 8; ni++) {
            *(uint2*)(QP + (qw + g) * QPSTR + (ni << 3) + (tig << 1)) =
                make_uint2(pr[ni][0], pr[ni][1]);
            *(uint2*)(QP + (qw + g + 8) * QPSTR + (ni << 3) + (tig << 1)) =
                make_uint2(pr[ni][2], pr[ni][3]);
        }
        __syncthreads();

        // ---- O += P @ V  (8 n-tiles over d, 8 k-steps over kseq) ----
#pragma unroll
        for (int ks = 0; ks < 8; ks++) {
            const int kk = (ks << 3) + tig;
            uint32_t af[4];
            const uint32_t* ap = QP + (qw + g) * QPSTR + kk;
            af[0] = ap[0];
            af[1] = ap[8 * QPSTR];
            af[2] = ap[4];
            af[3] = ap[8 * QPSTR + 4];
#pragma unroll
            for (int ni = 0; ni < 8; ni++) {
                uint32_t bf[2];
                const uint32_t* p = Vs + kk * AVSTR + (ni << 3) + g;
                bf[0] = p[0];
                bf[1] = p[4 * AVSTR];
                mma_tf32(o[ni], af, bf);
            }
        }
    }

    // ---- Epilogue: normalize, write O [B,S,H*Dk] ----
    const float rl0 = 1.f / l0, rl1 = 1.f / l1;
    const int row0 = q0 + qw + g;
#pragma unroll
    for (int ni = 0; ni < 8; ni++) {
        const int d = (ni << 3) + (tig << 1);
        *(float2*)(Og + hb + (size_t)row0 * D_MODEL + d) =
            make_float2(o[ni][0] * rl0, o[ni][1] * rl0);
        *(float2*)(Og + hb + (size_t)(row0 + 8) * D_MODEL + d) =
            make_float2(o[ni][2] * rl1, o[ni][3] * rl1);
    }
}

// ---------------------------------------------------------------------------
extern "C" void kernel_launch(void* const* d_in, const int* in_sizes, int n_in,
                              void* d_out, int out_size)
{
    const float* x  = (const float*)d_in[0];
    const float* Wq = (const float*)d_in[1];
    const float* bq = (const float*)d_in[2];
    const float* Wk = (const float*)d_in[3];
    const float* bk = (const float*)d_in[4];
    const float* Wv = (const float*)d_in[5];
    const float* bv = (const float*)d_in[6];
    const float* Wo = (const float*)d_in[7];
    const float* bo = (const float*)d_in[8];
    float* out = (float*)d_out;

    float *Qp, *Kp, *Vp, *Op;
    cudaGetSymbolAddress((void**)&Qp, g_Q);
    cudaGetSymbolAddress((void**)&Kp, g_K);
    cudaGetSymbolAddress((void**)&Vp, g_V);
    cudaGetSymbolAddress((void**)&Op, g_O);

    cudaFuncSetAttribute(gemm_tc, cudaFuncAttributeMaxDynamicSharedMemorySize,
                         GSMEM_BYTES);
    cudaFuncSetAttribute(attn_kernel, cudaFuncAttributeMaxDynamicSharedMemorySize,
                         ATTN_SMEM_B);

    dim3 gg(D_MODEL / TN, MTOT / TM);   // (8, 32)
    gemm_tc<<<gg, 256, GSMEM_BYTES>>>(x, Wq, bq, Qp);
    gemm_tc<<<gg, 256, GSMEM_BYTES>>>(x, Wk, bk, Kp);
    gemm_tc<<<gg, 256, GSMEM_BYTES>>>(x, Wv, bv, Vp);

    dim3 ga(SEQ / AQT, NUM_HEADS, BATCH);  // (16, 16, 2)
    attn_kernel<<<ga, 256, ATTN_SMEM_B>>>(Qp, Kp, Vp, Op);

    gemm_tc<<<gg, 256, GSMEM_BYTES>>>(Op, Wo, bo, out);
}